// round 9
// baseline (speedup 1.0000x reference)
#include <cuda_runtime.h>
#include <cstdint>
#include <math.h>

// Problem constants (fixed by the reference)
#define T_STEPS 250
#define NCH     3
#define DFEAT   40
#define IN_DIM  120     // NCH*DFEAT
#define NHID    200
#define NBR     8
#define PER     15      // IN_DIM / NBR
#define PERP    16      // padded per-branch stride in xbuf
#define XPAD    (NBR*PERP)   // 128
#define ODIM    35
#define NB      4       // batch elements per CTA
#define THREADS 448     // reg cap 146/thread -> no spill
#define NPROD   416     // warps 0..12 run the neuron phase
#define RSLOTS  (NB*ODIM)    // 140 readout slots (batch, output)
#define W2S     204     // W2 row stride (floats): 8 rows/warp -> distinct banks

// ---------------- packed f32x2 helpers (sm_100a) ----------------
__device__ __forceinline__ unsigned long long ffma2(unsigned long long a,
                                                    unsigned long long b,
                                                    unsigned long long c) {
    unsigned long long d;
    asm("fma.rn.f32x2 %0, %1, %2, %3;" : "=l"(d) : "l"(a), "l"(b), "l"(c));
    return d;
}
__device__ __forceinline__ unsigned long long add2(unsigned long long a,
                                                   unsigned long long b) {
    unsigned long long d;
    asm("add.rn.f32x2 %0, %1, %2;" : "=l"(d) : "l"(a), "l"(b));
    return d;
}
__device__ __forceinline__ unsigned long long pack2(float lo, float hi) {
    unsigned long long u;
    asm("mov.b64 %0, {%1, %2};" : "=l"(u) : "f"(lo), "f"(hi));
    return u;
}
__device__ __forceinline__ float2 unpack2(unsigned long long u) {
    float lo, hi;
    asm("mov.b64 {%0, %1}, %2;" : "=f"(lo), "=f"(hi) : "l"(u));
    return make_float2(lo, hi);
}
__device__ __forceinline__ float sigmoid_acc(float v) {
    return 1.0f / (1.0f + expf(-v));
}

// One CTA = 4 batch elements, grid 128 = one wave. Neuron phase: thread owns
// 2 neurons x 2 branches (kp, kp+4) -> x SMEM reads halved vs 4-branch/thread;
// somatic sum reduced over 4 lanes via shfl. Readout: 140 threads each do the
// full 200-dot for one (batch, output) slot and integrate in registers -> no
// psum stage, 2 barriers/step instead of 3.
__global__ void __launch_bounds__(THREADS, 1) snn_kernel(
    const float* __restrict__ x,       // [B, 3, 250, 40]
    const float* __restrict__ W1,      // [200, 8, 120]
    const float* __restrict__ b1,      // [200]
    const float* __restrict__ tau_m1,  // [200]
    const float* __restrict__ tau_n1,  // [200, 8]
    const float* __restrict__ W2,      // [35, 200]
    const float* __restrict__ b2,      // [35]
    const float* __restrict__ tau_m2,  // [35]
    float* __restrict__ out,           // [B, 35]
    int B)
{
    __shared__ __align__(16) float xbuf[NB][XPAD];     // branch-padded xt
    __shared__ __align__(16) float spk_s[NB][NHID];    // spikes (800B rows)
    __shared__ __align__(16) float w2s[ODIM][W2S];     // W2 rows, bank-spread
    __shared__ float accbuf[NB][ODIM];                 // integrator results

    const int tid = threadIdx.x;
    const int b0  = blockIdx.x * NB;

    // ---- one-time: W2 rows into SMEM; zero xbuf pad slots ----
    for (int idx = tid; idx < ODIM * NHID; idx += THREADS) {
        const int o = idx / NHID, n = idx % NHID;
        w2s[o][n] = W2[o * NHID + n];
    }
    if (tid < NB * NBR)
        xbuf[tid >> 3][(tid & 7) * PERP + PER] = 0.0f;   // pad j=15

    // ============ neuron-role init (tid < 416; warp 12 tail = dummies) ====
    const int u   = tid & 7;           // sub-role within neuron quad
    const int g   = tid >> 3;          // neuron quad id
    const int kp  = u & 3;             // branch pair {kp, kp+4}
    const int sxx = u >> 2;            // neuron sub-pair
    const int n0  = g * 4 + sxx * 2;   // first of 2 neurons
    const int ncl = (n0 < NHID) ? n0 : 196;   // clamp for dummy threads
    const int kA = kp, kB = kp + 4;

    unsigned long long wpA[2][7], wpB[2][7];
    float w14A[2], w14B[2], betaA[2], betaB[2];
    float dstA[NB][2], dstB[NB][2];
    float mem1[NB][2], spkr[NB][2];
    float alpha1[2], oma1[2], b1n[2];
#pragma unroll
    for (int bl = 0; bl < NB; bl++)
#pragma unroll
        for (int m = 0; m < 2; m++) {
            dstA[bl][m] = 0.f; dstB[bl][m] = 0.f;
            mem1[bl][m] = 0.f; spkr[bl][m] = 0.f;
        }
    if (tid < NPROD) {
#pragma unroll
        for (int m = 0; m < 2; m++) {
            const int n = ncl + m;
            alpha1[m] = sigmoid_acc(tau_m1[n]);
            oma1[m]   = 1.0f - alpha1[m];
            b1n[m]    = b1[n];
            betaA[m]  = sigmoid_acc(tau_n1[n * NBR + kA]);
            betaB[m]  = sigmoid_acc(tau_n1[n * NBR + kB]);
            const float* wrA = W1 + (size_t)(n * NBR + kA) * IN_DIM + kA * PER;
            const float* wrB = W1 + (size_t)(n * NBR + kB) * IN_DIM + kB * PER;
#pragma unroll
            for (int j = 0; j < 7; j++) {
                wpA[m][j] = pack2(wrA[2 * j], wrA[2 * j + 1]);
                wpB[m][j] = pack2(wrB[2 * j], wrB[2 * j + 1]);
            }
            w14A[m] = wrA[14];
            w14B[m] = wrB[14];
        }
    } else {
#pragma unroll
        for (int m = 0; m < 2; m++) {
#pragma unroll
            for (int j = 0; j < 7; j++) { wpA[m][j] = 0ull; wpB[m][j] = 0ull; }
            w14A[m] = w14B[m] = betaA[m] = betaB[m] = 0.f;
            alpha1[m] = oma1[m] = b1n[m] = 0.f;
        }
    }

    // ============ readout-role init (tid < 140) ============
    const int blr = tid & 3;
    const int orr = tid >> 2;          // < 35 when tid < 140
    float alpha2 = 0.f, oma2 = 0.f, b2o = 0.f, mem2 = 0.f, acc2 = 0.f;
    if (tid < RSLOTS) {
        alpha2 = sigmoid_acc(tau_m2[orr]);
        oma2   = 1.0f - alpha2;
        b2o    = b2[orr];
    }

    // ============ x ingest: 448 threads x1 + first 32 x2 ============
    const int bl1 = tid / IN_DIM, i1 = tid % IN_DIM;
    int bb1 = b0 + bl1; if (bb1 > B - 1) bb1 = B - 1;
    const float* pf1 = x + ((size_t)bb1 * NCH + i1 / DFEAT) * T_STEPS * DFEAT
                         + (i1 % DFEAT);
    const int of1 = bl1 * XPAD + (i1 / PER) * PERP + (i1 % PER);
    const bool two = (tid < NB * IN_DIM - THREADS);          // tid < 32
    const int e2 = THREADS + tid;
    const int bl2 = e2 / IN_DIM, i2 = e2 % IN_DIM;
    int bb2 = b0 + bl2; if (bb2 > B - 1) bb2 = B - 1;
    const float* pf2 = x + ((size_t)bb2 * NCH + i2 / DFEAT) * T_STEPS * DFEAT
                         + (i2 % DFEAT);
    const int of2 = bl2 * XPAD + (i2 / PER) * PERP + (i2 % PER);
    float xr1 = pf1[0];
    float xr2 = two ? pf2[0] : 0.f;

    float* const xb = &xbuf[0][0];

    // ============================ time loop ============================
#pragma unroll 1
    for (int t = 0; t < T_STEPS; t++) {
        // scatter xt (register -> padded smem)
        xb[of1] = xr1;
        if (two) xb[of2] = xr2;
        __syncthreads();   // S1: xt visible; prior readout spike-reads done

        // prefetch t+1 (hidden under neuron compute)
        {
            const int tn = (t + 1 < T_STEPS) ? t + 1 : t;
            xr1 = pf1[(size_t)tn * DFEAT];
            if (two) xr2 = pf2[(size_t)tn * DFEAT];
        }

        // ---- neuron phase: 2 neurons x 2 branches per thread ----
        if (tid < NPROD) {
#pragma unroll
            for (int bl = 0; bl < NB; bl++) {
                const ulonglong2* pA =
                    (const ulonglong2*)(xb + bl * XPAD + kA * PERP);
                ulonglong2 qA0 = pA[0], qA1 = pA[1], qA2 = pA[2], qA3 = pA[3];
                const ulonglong2* pB = pA + 4 * (PERP / 4);   // branch kB
                ulonglong2 qB0 = pB[0], qB1 = pB[1], qB2 = pB[2], qB3 = pB[3];
                const float x14A = unpack2(qA3.y).x;
                const float x14B = unpack2(qB3.y).x;

                float lh0, lh1;
#pragma unroll
                for (int m = 0; m < 2; m++) {
                    unsigned long long a0, a1;
                    a0 = ffma2(wpA[m][0], qA0.x, 0ull);
                    a1 = ffma2(wpA[m][1], qA0.y, 0ull);
                    a0 = ffma2(wpA[m][2], qA1.x, a0);
                    a1 = ffma2(wpA[m][3], qA1.y, a1);
                    a0 = ffma2(wpA[m][4], qA2.x, a0);
                    a1 = ffma2(wpA[m][5], qA2.y, a1);
                    a0 = ffma2(wpA[m][6], qA3.x, a0);
                    float2 vA = unpack2(add2(a0, a1));
                    float IA = fmaf(w14A[m], x14A, vA.x + vA.y);

                    unsigned long long c0, c1;
                    c0 = ffma2(wpB[m][0], qB0.x, 0ull);
                    c1 = ffma2(wpB[m][1], qB0.y, 0ull);
                    c0 = ffma2(wpB[m][2], qB1.x, c0);
                    c1 = ffma2(wpB[m][3], qB1.y, c1);
                    c0 = ffma2(wpB[m][4], qB2.x, c0);
                    c1 = ffma2(wpB[m][5], qB2.y, c1);
                    c0 = ffma2(wpB[m][6], qB3.x, c0);
                    float2 vB = unpack2(add2(c0, c1));
                    float IB = fmaf(w14B[m], x14B, vB.x + vB.y);

                    float dA = dstA[bl][m];
                    dA = fmaf(betaA[m], dA - IA, IA);
                    dstA[bl][m] = dA;
                    float dB = dstB[bl][m];
                    dB = fmaf(betaB[m], dB - IB, IB);
                    dstB[bl][m] = dB;
                    if (m == 0) lh0 = dA + dB; else lh1 = dA + dB;
                }
                // reduce across the 4 branch-pair lanes (4-aligned group)
                lh0 += __shfl_xor_sync(0xFFFFFFFFu, lh0, 1);
                lh0 += __shfl_xor_sync(0xFFFFFFFFu, lh0, 2);
                lh1 += __shfl_xor_sync(0xFFFFFFFFu, lh1, 1);
                lh1 += __shfl_xor_sync(0xFFFFFFFFu, lh1, 2);

                // LIF (replicated on all 4 lanes; identical inputs)
                float s0, s1;
                {
                    const float l = lh0 + b1n[0];
                    float m1 = fmaf(alpha1[0], mem1[bl][0] - spkr[bl][0],
                                    oma1[0] * l);
                    mem1[bl][0] = m1;
                    s0 = (m1 > 1.0f) ? 1.0f : 0.0f;
                    spkr[bl][0] = s0;
                }
                {
                    const float l = lh1 + b1n[1];
                    float m1 = fmaf(alpha1[1], mem1[bl][1] - spkr[bl][1],
                                    oma1[1] * l);
                    mem1[bl][1] = m1;
                    s1 = (m1 > 1.0f) ? 1.0f : 0.0f;
                    spkr[bl][1] = s1;
                }
                if (kp == 0 && n0 < NHID)
                    *(float2*)&spk_s[bl][n0] = make_float2(s0, s1);
            }
        }
        __syncthreads();   // S2: spikes visible

        // ---- readout + integrator: full 200-dot per (batch, output) ----
        if (tid < RSLOTS) {
            const ulonglong2* sp = (const ulonglong2*)&spk_s[blr][0];
            const ulonglong2* wv = (const ulonglong2*)&w2s[orr][0];
            unsigned long long a0 = 0ull, a1 = 0ull;
#pragma unroll 10
            for (int j = 0; j < NHID / 4; j++) {   // 50 x 4 floats
                ulonglong2 wj = wv[j];
                ulonglong2 sj = sp[j];
                a0 = ffma2(wj.x, sj.x, a0);
                a1 = ffma2(wj.y, sj.y, a1);
            }
            float2 dv = unpack2(add2(a0, a1));
            const float z = dv.x + dv.y + b2o;
            mem2 = fmaf(alpha2, mem2, oma2 * z);
            acc2 += mem2;
        }
        // next S1 orders readout spike-reads vs. next spike-writes
    }

    // ==================== epilogue: log_softmax(acc/T) ====================
    if (tid < RSLOTS) accbuf[blr][orr] = acc2 * (1.0f / (float)T_STEPS);
    __syncthreads();
    if (tid < RSLOTS) {
        const int b = b0 + blr;
        if (b < B) {
            float m = -INFINITY;
#pragma unroll
            for (int j = 0; j < ODIM; j++) m = fmaxf(m, accbuf[blr][j]);
            float ssum = 0.0f;
#pragma unroll
            for (int j = 0; j < ODIM; j++) ssum += expf(accbuf[blr][j] - m);
            out[(size_t)b * ODIM + orr] = accbuf[blr][orr] - m - logf(ssum);
        }
    }
}

extern "C" void kernel_launch(void* const* d_in, const int* in_sizes, int n_in,
                              void* d_out, int out_size) {
    const float* x      = (const float*)d_in[0];
    const float* W1     = (const float*)d_in[1];
    const float* b1     = (const float*)d_in[2];
    const float* tau_m1 = (const float*)d_in[3];
    const float* tau_n1 = (const float*)d_in[4];
    const float* W2     = (const float*)d_in[5];
    const float* b2     = (const float*)d_in[6];
    const float* tau_m2 = (const float*)d_in[7];
    float* out = (float*)d_out;

    const int B = in_sizes[0] / (NCH * T_STEPS * DFEAT);   // 512
    const int grid = (B + NB - 1) / NB;                    // 128
    snn_kernel<<<grid, THREADS>>>(x, W1, b1, tau_m1, tau_n1, W2, b2, tau_m2,
                                  out, B);
}

// round 10
// speedup vs baseline: 1.7078x; 1.7078x over previous
#include <cuda_runtime.h>
#include <cstdint>
#include <math.h>

// Problem constants (fixed by the reference)
#define T_STEPS 250
#define NCH     3
#define DFEAT   40
#define IN_DIM  120     // NCH*DFEAT
#define NHID    200
#define NHPAD   224     // spike row padded (zero tail) for 7x32 readout chunks
#define NBR     8
#define PER     15      // IN_DIM / NBR
#define PERP    16      // padded per-branch stride in xbuf (16B-aligned pairs)
#define XPAD    (NBR*PERP)   // 128
#define ODIM    35
#define NB      4       // batch elements per CTA
#define NPARTS  7       // readout partial-sum parts (7*32 = 224)
#define W2S     228     // w2s row stride: rows start 4 banks apart -> 8 rows
                        // cover all 32 banks (conflict-free 32-row access)
#define THREADS 256

// ---------------- packed f32x2 helpers (sm_100a) ----------------
__device__ __forceinline__ unsigned long long ffma2(unsigned long long a,
                                                    unsigned long long b,
                                                    unsigned long long c) {
    unsigned long long d;
    asm("fma.rn.f32x2 %0, %1, %2, %3;" : "=l"(d) : "l"(a), "l"(b), "l"(c));
    return d;
}
__device__ __forceinline__ unsigned long long add2(unsigned long long a,
                                                   unsigned long long b) {
    unsigned long long d;
    asm("add.rn.f32x2 %0, %1, %2;" : "=l"(d) : "l"(a), "l"(b));
    return d;
}
__device__ __forceinline__ unsigned long long pack2(float lo, float hi) {
    unsigned long long u;
    asm("mov.b64 %0, {%1, %2};" : "=l"(u) : "f"(lo), "f"(hi));
    return u;
}
__device__ __forceinline__ float2 unpack2(unsigned long long u) {
    float lo, hi;
    asm("mov.b64 {%0, %1}, %2;" : "=f"(lo), "=f"(hi) : "l"(u));
    return make_float2(lo, hi);
}
__device__ __forceinline__ float sigmoid_acc(float v) {
    return 1.0f / (1.0f + expf(-v));
}
// Volatile LDS.128: compiler cannot hoist it out of the time loop into
// persistent registers (that hoist is what pushed R4 to the 255-reg cap).
__device__ __forceinline__ float4 lds128v(uint32_t addr) {
    float4 v;
    asm volatile("ld.shared.v4.f32 {%0,%1,%2,%3}, [%4];"
                 : "=f"(v.x), "=f"(v.y), "=f"(v.z), "=f"(v.w) : "r"(addr));
    return v;
}

// One CTA handles NB=4 batch elements (grid 128 = one wave). Thread n (<200)
// owns neuron n for all 4 batches; dendritic weights live in registers.
// R4 architecture with W2 moved from registers to SMEM -> no spilling.
__global__ void __launch_bounds__(THREADS, 1) snn_kernel(
    const float* __restrict__ x,       // [B, 3, 250, 40]
    const float* __restrict__ W1,      // [200, 8, 120]
    const float* __restrict__ b1,      // [200]
    const float* __restrict__ tau_m1,  // [200]
    const float* __restrict__ tau_n1,  // [200, 8]
    const float* __restrict__ W2,      // [35, 200]
    const float* __restrict__ b2,      // [35]
    const float* __restrict__ tau_m2,  // [35]
    float* __restrict__ out,           // [B, 35]
    int B)
{
    __shared__ __align__(16) float xbuf[NB][XPAD];        // branch-padded xt
    __shared__ __align__(16) float spk_s[NB][NHPAD];      // spikes, zero tail
    __shared__ __align__(16) float w2s[ODIM][W2S];        // W2 rows, zero tail
    __shared__ float psum[NPARTS][NB][ODIM + 1];          // readout partials
    __shared__ float accbuf[NB][ODIM];                    // log-softmax staging

    const int tid = threadIdx.x;
    const int b0  = blockIdx.x * NB;

    // ---- one-time: W2 rows (zero-padded) + spike tails ----
    for (int idx = tid; idx < ODIM * W2S; idx += THREADS) {
        const int o = idx / W2S, n = idx % W2S;
        w2s[o][n] = (n < NHID) ? W2[o * NHID + n] : 0.0f;
    }
    for (int idx = tid; idx < NB * (NHPAD - NHID); idx += THREADS)
        spk_s[idx / (NHPAD - NHID)][NHID + idx % (NHPAD - NHID)] = 0.0f;

    // ================= per-neuron params + packed weights =================
    unsigned long long wp[NBR * 7];   // 7 packed pairs per branch
    float w14[NBR];                   // 15th (scalar) weight per branch
    float beta[NBR];
    float dst[NB][NBR];
    float mem1[NB], spk[NB];
    float alpha1 = 0.f, oma1 = 0.f, b1n = 0.f;
#pragma unroll
    for (int bl = 0; bl < NB; bl++) {
        mem1[bl] = 0.f; spk[bl] = 0.f;
#pragma unroll
        for (int k = 0; k < NBR; k++) dst[bl][k] = 0.f;
    }
    if (tid < NHID) {
        const int n = tid;
        alpha1 = sigmoid_acc(tau_m1[n]);
        oma1   = 1.0f - alpha1;
        b1n    = b1[n];
#pragma unroll
        for (int k = 0; k < NBR; k++) {
            beta[k] = sigmoid_acc(tau_n1[n * NBR + k]);
            const float* wrow = W1 + (size_t)(n * NBR + k) * IN_DIM + k * PER;
#pragma unroll
            for (int j = 0; j < 7; j++)
                wp[k * 7 + j] = pack2(wrow[2 * j], wrow[2 * j + 1]);
            w14[k] = wrow[14];
        }
    } else {
#pragma unroll
        for (int m = 0; m < NBR * 7; m++) wp[m] = 0ull;
#pragma unroll
        for (int k = 0; k < NBR; k++) { beta[k] = 0.f; w14[k] = 0.f; }
    }

    // ================= readout role: W2 chunk base address =================
    const int p_ro = (tid / ODIM < NPARTS - 1) ? tid / ODIM : NPARTS - 1;
    const int o_ro = tid % ODIM;
    const int np0  = p_ro * 32;            // 32-neuron chunk, zero-padded tail
    const uint32_t w2a =
        (uint32_t)__cvta_generic_to_shared(&w2s[o_ro][np0]);

    // ================= integrator params (threads 0..139) =================
    float alpha2 = 0.f, oma2 = 0.f, b2o = 0.f, mem2 = 0.f, acc = 0.f;
    if (tid < NB * ODIM) {
        alpha2 = sigmoid_acc(tau_m2[o_ro]);   // o_ro == tid % ODIM
        oma2   = 1.0f - alpha2;
        b2o    = b2[o_ro];
    }

    // ================= x prefetch: 240 threads x 2 floats =================
    const float* pf_ptr = nullptr;
    float*       sl0 = nullptr;
    float*       sl1 = nullptr;
    float2 xr = make_float2(0.f, 0.f);
    if (tid < (NB * IN_DIM) / 2) {
        const int g   = 2 * tid;
        const int blp = g / IN_DIM;
        const int i0  = g % IN_DIM;
        const int c   = i0 / DFEAT;
        const int d   = i0 % DFEAT;
        int bb = b0 + blp; if (bb > B - 1) bb = B - 1;
        pf_ptr = x + ((size_t)bb * NCH + c) * T_STEPS * DFEAT + d;
        sl0 = &xbuf[blp][(i0 / PER) * PERP + (i0 % PER)];
        const int i1 = i0 + 1;
        sl1 = &xbuf[blp][(i1 / PER) * PERP + (i1 % PER)];
        xr = *(const float2*)pf_ptr;           // t = 0
    }

    __syncthreads();   // w2s, spike tails, xr(t=0) ready

    // ============================ time loop ============================
#pragma unroll 1
    for (int t = 0; t < T_STEPS; t++) {
        // scatter xt (register -> padded smem)
        if (pf_ptr) { *sl0 = xr.x; *sl1 = xr.y; }
        __syncthreads();   // S1: xbuf ready; prior psum/spk consumers done

        // prefetch t+1 (hides DRAM latency under this step's compute)
        if (pf_ptr) {
            const int tn = (t + 1 < T_STEPS) ? t + 1 : t;
            xr = *(const float2*)(pf_ptr + (size_t)tn * DFEAT);
        }

        // ---- neuron phase: dendrites -> soma -> spike, all 4 batches ----
        if (tid < NHID) {
#pragma unroll
            for (int bl = 0; bl < NB; bl++) {
                float l = b1n;
#pragma unroll
                for (int k = 0; k < NBR; k++) {
                    const ulonglong2* xp =
                        (const ulonglong2*)(&xbuf[bl][k * PERP]);
                    ulonglong2 q0 = xp[0];
                    ulonglong2 q1 = xp[1];
                    unsigned long long a0, a1;
                    a0 = ffma2(wp[k * 7 + 0], q0.x, 0ull);
                    a1 = ffma2(wp[k * 7 + 1], q0.y, 0ull);
                    a0 = ffma2(wp[k * 7 + 2], q1.x, a0);
                    a1 = ffma2(wp[k * 7 + 3], q1.y, a1);
                    ulonglong2 q2 = xp[2];
                    a0 = ffma2(wp[k * 7 + 4], q2.x, a0);
                    a1 = ffma2(wp[k * 7 + 5], q2.y, a1);
                    ulonglong2 q3 = xp[3];
                    a0 = ffma2(wp[k * 7 + 6], q3.x, a0);
                    float2 vv  = unpack2(add2(a0, a1));
                    float2 hx  = unpack2(q3.y);          // (x14, pad-unused)
                    float  I   = fmaf(w14[k], hx.x, vv.x + vv.y);
                    float  dk  = dst[bl][k];
                    dk = fmaf(beta[k], dk - I, I);       // beta*d + (1-beta)*I
                    dst[bl][k] = dk;
                    l += dk;
                }
                // soft-reset LIF
                float m = fmaf(alpha1, mem1[bl] - spk[bl], oma1 * l);
                mem1[bl] = m;
                float s = (m > 1.0f) ? 1.0f : 0.0f;
                spk[bl] = s;
                spk_s[bl][tid] = s;
            }
        }
        __syncthreads();   // S2: spikes visible

        // ---- readout partials: W2 chunk reloaded per step (not hoisted) ----
        if (tid < NPARTS * ODIM) {
            float4 wq0 = lds128v(w2a +  0);
            float4 wq1 = lds128v(w2a + 16);
            float4 wq2 = lds128v(w2a + 32);
            float4 wq3 = lds128v(w2a + 48);
            float4 wq4 = lds128v(w2a + 64);
            float4 wq5 = lds128v(w2a + 80);
            float4 wq6 = lds128v(w2a + 96);
            float4 wq7 = lds128v(w2a + 112);
#pragma unroll
            for (int bl = 0; bl < NB; bl++) {
                const float4* sp = (const float4*)(&spk_s[bl][np0]);
                float s0 = 0.f, s1 = 0.f;
                float4 v;
                v = sp[0];
                s0 = fmaf(v.x, wq0.x, s0); s1 = fmaf(v.y, wq0.y, s1);
                s0 = fmaf(v.z, wq0.z, s0); s1 = fmaf(v.w, wq0.w, s1);
                v = sp[1];
                s0 = fmaf(v.x, wq1.x, s0); s1 = fmaf(v.y, wq1.y, s1);
                s0 = fmaf(v.z, wq1.z, s0); s1 = fmaf(v.w, wq1.w, s1);
                v = sp[2];
                s0 = fmaf(v.x, wq2.x, s0); s1 = fmaf(v.y, wq2.y, s1);
                s0 = fmaf(v.z, wq2.z, s0); s1 = fmaf(v.w, wq2.w, s1);
                v = sp[3];
                s0 = fmaf(v.x, wq3.x, s0); s1 = fmaf(v.y, wq3.y, s1);
                s0 = fmaf(v.z, wq3.z, s0); s1 = fmaf(v.w, wq3.w, s1);
                v = sp[4];
                s0 = fmaf(v.x, wq4.x, s0); s1 = fmaf(v.y, wq4.y, s1);
                s0 = fmaf(v.z, wq4.z, s0); s1 = fmaf(v.w, wq4.w, s1);
                v = sp[5];
                s0 = fmaf(v.x, wq5.x, s0); s1 = fmaf(v.y, wq5.y, s1);
                s0 = fmaf(v.z, wq5.z, s0); s1 = fmaf(v.w, wq5.w, s1);
                v = sp[6];
                s0 = fmaf(v.x, wq6.x, s0); s1 = fmaf(v.y, wq6.y, s1);
                s0 = fmaf(v.z, wq6.z, s0); s1 = fmaf(v.w, wq6.w, s1);
                v = sp[7];
                s0 = fmaf(v.x, wq7.x, s0); s1 = fmaf(v.y, wq7.y, s1);
                s0 = fmaf(v.z, wq7.z, s0); s1 = fmaf(v.w, wq7.w, s1);
                psum[p_ro][bl][o_ro] = s0 + s1;
            }
        }
        __syncthreads();   // S3: partials visible

        // ---- leaky readout integrator: thread (bl, o) ----
        if (tid < NB * ODIM) {
            const int bl = tid / ODIM;
            float z = b2o;
#pragma unroll
            for (int p = 0; p < NPARTS; p++) z += psum[p][bl][o_ro];
            mem2 = fmaf(alpha2, mem2, oma2 * z);
            acc += mem2;
        }
        // next iteration's S1 orders psum/spk reuse
    }

    // ==================== epilogue: log_softmax(acc/T) ====================
    if (tid < NB * ODIM) accbuf[tid / ODIM][o_ro] = acc * (1.0f / (float)T_STEPS);
    __syncthreads();
    if (tid < NB * ODIM) {
        const int bl = tid / ODIM;
        const int b  = b0 + bl;
        if (b < B) {
            float m = -INFINITY;
#pragma unroll
            for (int o = 0; o < ODIM; o++) m = fmaxf(m, accbuf[bl][o]);
            float ssum = 0.0f;
#pragma unroll
            for (int o = 0; o < ODIM; o++) ssum += expf(accbuf[bl][o] - m);
            out[(size_t)b * ODIM + o_ro] = accbuf[bl][o_ro] - m - logf(ssum);
        }
    }
}

extern "C" void kernel_launch(void* const* d_in, const int* in_sizes, int n_in,
                              void* d_out, int out_size) {
    const float* x      = (const float*)d_in[0];
    const float* W1     = (const float*)d_in[1];
    const float* b1     = (const float*)d_in[2];
    const float* tau_m1 = (const float*)d_in[3];
    const float* tau_n1 = (const float*)d_in[4];
    const float* W2     = (const float*)d_in[5];
    const float* b2     = (const float*)d_in[6];
    const float* tau_m2 = (const float*)d_in[7];
    float* out = (float*)d_out;

    const int B = in_sizes[0] / (NCH * T_STEPS * DFEAT);   // 512
    const int grid = (B + NB - 1) / NB;                    // 128
    snn_kernel<<<grid, THREADS>>>(x, W1, b1, tau_m1, tau_n1, W2, b2, tau_m2,
                                  out, B);
}

// round 12
// speedup vs baseline: 1.7561x; 1.0283x over previous
#include <cuda_runtime.h>
#include <cstdint>
#include <math.h>

// Problem constants (fixed by the reference)
#define T_STEPS 250
#define NCH     3
#define DFEAT   40
#define IN_DIM  120     // NCH*DFEAT
#define NHID    200
#define NHPAD   224     // spike row padded (zero tail) for 7x32 readout chunks
#define NBR     8
#define PER     15      // IN_DIM / NBR
#define PERP    16      // padded per-branch stride in xbuf (16B-aligned pairs)
#define XPAD    (NBR*PERP)   // 128
#define ODIM    35
#define NB      4       // batch elements per CTA
#define NPARTS  7       // readout partial-sum parts (7*32 = 224)
#define TB      2       // time-block: steps per barrier phase
#define NPHASE  (T_STEPS/TB)   // 125
#define THREADS 256

// ---------------- packed f32x2 helpers (sm_100a) ----------------
__device__ __forceinline__ unsigned long long ffma2(unsigned long long a,
                                                    unsigned long long b,
                                                    unsigned long long c) {
    unsigned long long d;
    asm("fma.rn.f32x2 %0, %1, %2, %3;" : "=l"(d) : "l"(a), "l"(b), "l"(c));
    return d;
}
__device__ __forceinline__ unsigned long long add2(unsigned long long a,
                                                   unsigned long long b) {
    unsigned long long d;
    asm("add.rn.f32x2 %0, %1, %2;" : "=l"(d) : "l"(a), "l"(b));
    return d;
}
__device__ __forceinline__ unsigned long long pack2(float lo, float hi) {
    unsigned long long u;
    asm("mov.b64 %0, {%1, %2};" : "=l"(u) : "f"(lo), "f"(hi));
    return u;
}
__device__ __forceinline__ float2 unpack2(unsigned long long u) {
    float lo, hi;
    asm("mov.b64 {%0, %1}, %2;" : "=f"(lo), "=f"(hi) : "l"(u));
    return make_float2(lo, hi);
}
__device__ __forceinline__ float sigmoid_acc(float v) {
    return 1.0f / (1.0f + expf(-v));
}
// Volatile LDG.128 (L1-cached, read-only): the volatile stops the compiler
// hoisting the loop-invariant W2 chunk into 32 persistent registers (which is
// what pinned R4 at the 255-reg cap).
__device__ __forceinline__ float4 ldg128v(const float* p) {
    float4 v;
    asm volatile("ld.global.nc.v4.f32 {%0,%1,%2,%3}, [%4];"
                 : "=f"(v.x), "=f"(v.y), "=f"(v.z), "=f"(v.w) : "l"(p));
    return v;
}

// One CTA handles NB=4 batch elements (grid 128 = one wave). Thread n (<200)
// owns neuron n for all 4 batches; dendritic weights live in registers.
// TB=2 time-blocking: the LIF recurrence is thread-local, so the neuron phase
// advances 2 steps between barriers -> 3 barriers per 2 steps instead of 3
// per step, and readout fetches its W2 chunk once per phase.
__global__ void __launch_bounds__(THREADS, 1) snn_kernel(
    const float* __restrict__ x,       // [B, 3, 250, 40]
    const float* __restrict__ W1,      // [200, 8, 120]
    const float* __restrict__ b1,      // [200]
    const float* __restrict__ tau_m1,  // [200]
    const float* __restrict__ tau_n1,  // [200, 8]
    const float* __restrict__ W2,      // [35, 200]
    const float* __restrict__ b2,      // [35]
    const float* __restrict__ tau_m2,  // [35]
    float* __restrict__ out,           // [B, 35]
    int B)
{
    __shared__ __align__(16) float xbuf[TB][NB][XPAD];    // per-step xt
    __shared__ __align__(16) float spk_s[TB][NB][NHPAD];  // spikes, zero tail
    __shared__ float psum[TB][NPARTS][NB][ODIM + 1];      // readout partials
    __shared__ float accbuf[NB][ODIM];                    // log-softmax staging

    const int tid = threadIdx.x;
    const int b0  = blockIdx.x * NB;

    // ---- one-time: zero spike tails + xbuf pad slots ----
    for (int idx = tid; idx < TB * NB * (NHPAD - NHID); idx += THREADS) {
        const int s  = idx / (NB * (NHPAD - NHID));
        const int r  = idx % (NB * (NHPAD - NHID));
        spk_s[s][r / (NHPAD - NHID)][NHID + r % (NHPAD - NHID)] = 0.0f;
    }
    if (tid < TB * NB * NBR) {
        const int s = tid / (NB * NBR);
        const int r = tid % (NB * NBR);
        xbuf[s][r >> 3][(r & 7) * PERP + PER] = 0.0f;     // pad j=15
    }

    // ================= per-neuron params + packed weights =================
    unsigned long long wp[NBR * 7];   // 7 packed pairs per branch
    float w14[NBR];                   // 15th (scalar) weight per branch
    float beta[NBR];
    float dst[NB][NBR];
    float mem1[NB], spk[NB];
    float alpha1 = 0.f, oma1 = 0.f, b1n = 0.f;
#pragma unroll
    for (int bl = 0; bl < NB; bl++) {
        mem1[bl] = 0.f; spk[bl] = 0.f;
#pragma unroll
        for (int k = 0; k < NBR; k++) dst[bl][k] = 0.f;
    }
    if (tid < NHID) {
        const int n = tid;
        alpha1 = sigmoid_acc(tau_m1[n]);
        oma1   = 1.0f - alpha1;
        b1n    = b1[n];
#pragma unroll
        for (int k = 0; k < NBR; k++) {
            beta[k] = sigmoid_acc(tau_n1[n * NBR + k]);
            const float* wrow = W1 + (size_t)(n * NBR + k) * IN_DIM + k * PER;
#pragma unroll
            for (int j = 0; j < 7; j++)
                wp[k * 7 + j] = pack2(wrow[2 * j], wrow[2 * j + 1]);
            w14[k] = wrow[14];
        }
    } else {
#pragma unroll
        for (int m = 0; m < NBR * 7; m++) wp[m] = 0ull;
#pragma unroll
        for (int k = 0; k < NBR; k++) { beta[k] = 0.f; w14[k] = 0.f; }
    }

    // ================= readout role: W2 chunk location =================
    const int p_ro = (tid / ODIM < NPARTS - 1) ? tid / ODIM : NPARTS - 1;
    const int o_ro = tid % ODIM;
    const int np0  = p_ro * 32;            // 32-neuron chunk (zero-pad tail)
    const float* const w2p = W2 + o_ro * NHID + np0;

    // ================= integrator params (threads 0..139) =================
    float alpha2 = 0.f, oma2 = 0.f, b2o = 0.f, mem2 = 0.f, acc = 0.f;
    if (tid < NB * ODIM) {
        alpha2 = sigmoid_acc(tau_m2[o_ro]);   // o_ro == tid % ODIM
        oma2   = 1.0f - alpha2;
        b2o    = b2[o_ro];
    }

    // ========= x prefetch: 240 threads x 2 floats x TB steps =========
    const float* pf_ptr = nullptr;
    int of0 = 0, of1 = 0;                 // element offsets within one buffer
    float2 xr0 = make_float2(0.f, 0.f);   // step 2t
    float2 xr1 = make_float2(0.f, 0.f);   // step 2t+1
    if (tid < (NB * IN_DIM) / 2) {
        const int g   = 2 * tid;
        const int blp = g / IN_DIM;
        const int i0  = g % IN_DIM;
        const int c   = i0 / DFEAT;
        const int d   = i0 % DFEAT;
        int bb = b0 + blp; if (bb > B - 1) bb = B - 1;
        pf_ptr = x + ((size_t)bb * NCH + c) * T_STEPS * DFEAT + d;
        of0 = blp * XPAD + (i0 / PER) * PERP + (i0 % PER);
        const int i1 = i0 + 1;
        of1 = blp * XPAD + (i1 / PER) * PERP + (i1 % PER);
        xr0 = *(const float2*)pf_ptr;                       // t = 0
        xr1 = *(const float2*)(pf_ptr + DFEAT);             // t = 1
    }

    float* const xb0 = &xbuf[0][0][0];
    float* const xb1 = &xbuf[1][0][0];

    __syncthreads();   // zeros + prefetch ready

    // ============================ phase loop ============================
#pragma unroll 1
    for (int t = 0; t < NPHASE; t++) {
        // scatter both steps' xt (registers -> padded smem)
        if (pf_ptr) {
            xb0[of0] = xr0.x; xb0[of1] = xr0.y;
            xb1[of0] = xr1.x; xb1[of1] = xr1.y;
        }
        __syncthreads();   // S1: xbuf ready; prior psum/spk consumers done

        // prefetch next phase (hidden under this phase's compute)
        if (pf_ptr) {
            int tn0 = 2 * t + 2; if (tn0 > T_STEPS - 1) tn0 = T_STEPS - 1;
            int tn1 = 2 * t + 3; if (tn1 > T_STEPS - 1) tn1 = T_STEPS - 1;
            xr0 = *(const float2*)(pf_ptr + (size_t)tn0 * DFEAT);
            xr1 = *(const float2*)(pf_ptr + (size_t)tn1 * DFEAT);
        }

        // ---- neuron phase: advance TB=2 steps, all 4 batches ----
        if (tid < NHID) {
#pragma unroll
            for (int s = 0; s < TB; s++) {
#pragma unroll
                for (int bl = 0; bl < NB; bl++) {
                    float l = b1n;
#pragma unroll
                    for (int k = 0; k < NBR; k++) {
                        const ulonglong2* xp =
                            (const ulonglong2*)(&xbuf[s][bl][k * PERP]);
                        ulonglong2 q0 = xp[0];
                        ulonglong2 q1 = xp[1];
                        unsigned long long a0, a1;
                        a0 = ffma2(wp[k * 7 + 0], q0.x, 0ull);
                        a1 = ffma2(wp[k * 7 + 1], q0.y, 0ull);
                        a0 = ffma2(wp[k * 7 + 2], q1.x, a0);
                        a1 = ffma2(wp[k * 7 + 3], q1.y, a1);
                        ulonglong2 q2 = xp[2];
                        a0 = ffma2(wp[k * 7 + 4], q2.x, a0);
                        a1 = ffma2(wp[k * 7 + 5], q2.y, a1);
                        ulonglong2 q3 = xp[3];
                        a0 = ffma2(wp[k * 7 + 6], q3.x, a0);
                        float2 vv  = unpack2(add2(a0, a1));
                        float2 hx  = unpack2(q3.y);        // (x14, pad)
                        float  I   = fmaf(w14[k], hx.x, vv.x + vv.y);
                        float  dk  = dst[bl][k];
                        dk = fmaf(beta[k], dk - I, I);     // beta*d+(1-beta)*I
                        dst[bl][k] = dk;
                        l += dk;
                    }
                    // soft-reset LIF
                    float m = fmaf(alpha1, mem1[bl] - spk[bl], oma1 * l);
                    mem1[bl] = m;
                    float sv = (m > 1.0f) ? 1.0f : 0.0f;
                    spk[bl] = sv;
                    spk_s[s][bl][tid] = sv;
                }
            }
        }
        __syncthreads();   // S2: both steps' spikes visible

        // ---- readout partials: W2 chunk via predicated LDG (L1-hot) ----
        if (tid < NPARTS * ODIM) {
            float4 wq[8];
#pragma unroll
            for (int j = 0; j < 8; j++) {
                const int nb_ = np0 + 4 * j;
                wq[j] = (nb_ + 3 < NHID) ? ldg128v(w2p + 4 * j)
                                         : make_float4(0.f, 0.f, 0.f, 0.f);
            }
#pragma unroll
            for (int s = 0; s < TB; s++) {
#pragma unroll
                for (int bl = 0; bl < NB; bl++) {
                    const float4* sp = (const float4*)(&spk_s[s][bl][np0]);
                    float s0 = 0.f, s1 = 0.f;
#pragma unroll
                    for (int q = 0; q < 8; q++) {
                        float4 v = sp[q];
                        s0 = fmaf(v.x, wq[q].x, s0);
                        s1 = fmaf(v.y, wq[q].y, s1);
                        s0 = fmaf(v.z, wq[q].z, s0);
                        s1 = fmaf(v.w, wq[q].w, s1);
                    }
                    psum[s][p_ro][bl][o_ro] = s0 + s1;
                }
            }
        }
        __syncthreads();   // S3: partials visible

        // ---- leaky readout integrator: thread (bl, o), both steps ----
        if (tid < NB * ODIM) {
            const int bl = tid / ODIM;
#pragma unroll
            for (int s = 0; s < TB; s++) {
                float z = b2o;
#pragma unroll
                for (int p = 0; p < NPARTS; p++) z += psum[s][p][bl][o_ro];
                mem2 = fmaf(alpha2, mem2, oma2 * z);
                acc += mem2;
            }
        }
        // next phase's S1 orders psum/spk reuse
    }

    // ==================== epilogue: log_softmax(acc/T) ====================
    if (tid < NB * ODIM) accbuf[tid / ODIM][o_ro] = acc * (1.0f / (float)T_STEPS);
    __syncthreads();
    if (tid < NB * ODIM) {
        const int bl = tid / ODIM;
        const int b  = b0 + bl;
        if (b < B) {
            float m = -INFINITY;
#pragma unroll
            for (int o = 0; o < ODIM; o++) m = fmaxf(m, accbuf[bl][o]);
            float ssum = 0.0f;
#pragma unroll
            for (int o = 0; o < ODIM; o++) ssum += expf(accbuf[bl][o] - m);
            out[(size_t)b * ODIM + o_ro] = accbuf[bl][o_ro] - m - logf(ssum);
        }
    }
}

extern "C" void kernel_launch(void* const* d_in, const int* in_sizes, int n_in,
                              void* d_out, int out_size) {
    const float* x      = (const float*)d_in[0];
    const float* W1     = (const float*)d_in[1];
    const float* b1     = (const float*)d_in[2];
    const float* tau_m1 = (const float*)d_in[3];
    const float* tau_n1 = (const float*)d_in[4];
    const float* W2     = (const float*)d_in[5];
    const float* b2     = (const float*)d_in[6];
    const float* tau_m2 = (const float*)d_in[7];
    float* out = (float*)d_out;

    const int B = in_sizes[0] / (NCH * T_STEPS * DFEAT);   // 512
    const int grid = (B + NB - 1) / NB;                    // 128
    snn_kernel<<<grid, THREADS>>>(x, W1, b1, tau_m1, tau_n1, W2, b2, tau_m2,
                                  out, B);
}